// round 2
// baseline (speedup 1.0000x reference)
#include <cuda_runtime.h>
#include <cuda_bf16.h>

// ChunkStickyRouter on GB300 (sm_103a)
// B=8, S=4096, D=2048, H=1024, E=8, CHUNK=128, TAU=0.7
//
// Pipeline:
//  k1: fused GEMM1 (x@W1 + b1, relu) with per-chunk row-sum epilogue -> g_hsum[256][1024]
//  k2: tiny GEMM2: chunk_logits = g_hsum @ W2 / 128 + b2            -> g_clogits[256][8]
//  k3: hysteresis scan per batch                                    -> g_eidx[256]
//  k4: one-hot fill of routing_weights [B,S,E] (+ indices tail if room)

#define B_  8
#define S_  4096
#define D_  2048
#define H_  1024
#define E_  8
#define CHUNK_ 128
#define NCHUNK_ 256   // B * S/CHUNK = 8*32
#define TAU_ 0.7f

#define BM 128
#define BN 64
#define BK 32
#define BMP 132   // padded M stride in smem (keeps 16B alignment: 132*4=528=16*33)

__device__ float g_hsum[NCHUNK_ * H_];
__device__ float g_clogits[NCHUNK_ * E_];
__device__ int   g_eidx[NCHUNK_];

// packed f32x2 FMA (PTX-only on sm_103a; ptxas will not auto-fuse)
#define FMA2(c, a, b) asm("fma.rn.f32x2 %0, %1, %2, %0;" : "+l"(c) : "l"(a), "l"(b))
#define DUP2(d, f)    asm("mov.b64 %0, {%1, %1};" : "=l"(d) : "r"(f))

__global__ __launch_bounds__(256, 2)
void gemm1_relu_chunksum(const float* __restrict__ x,
                         const float* __restrict__ W1,
                         const float* __restrict__ b1) {
    __shared__ __align__(16) float As[BK][BMP];  // transposed x tile [k][m]
    __shared__ __align__(16) float Bs[BK][BN];   // W1 tile [k][n]
    __shared__ float Red[16][BN + 4];            // cross-ty reduction

    const int chunk = blockIdx.y;        // 0..255 (== token/128)
    const int n0    = blockIdx.x * BN;   // 0..960
    const int m0    = chunk * BM;

    const int tid = threadIdx.x;
    const int tx  = tid & 15;   // n group: n = n0 + tx*4 + {0..3}
    const int ty  = tid >> 4;   // m group: m = ty*8 + {0..7}

    // load-index precompute
    const int lr  = tid >> 3;         // x-tile row within pass (0..31)
    const int lc  = (tid & 7) * 4;    // x-tile k col (float4)
    const int br  = tid >> 4;         // W1-tile row (0..15)
    const int bc4 = (tid & 15) * 4;   // W1-tile n col (float4)

    const float* xblk = x + (size_t)m0 * D_;

    unsigned long long acc[4][4];     // [m-pair][n], each packs 2 fp32
    #pragma unroll
    for (int i = 0; i < 4; i++)
        #pragma unroll
        for (int j = 0; j < 4; j++) acc[i][j] = 0ULL;

    float4 xa[4];
    float4 wb[2];

    // prologue: load tile k0=0 into regs
    #pragma unroll
    for (int p = 0; p < 4; p++)
        xa[p] = *(const float4*)(xblk + (size_t)(lr + p * 32) * D_ + lc);
    #pragma unroll
    for (int p = 0; p < 2; p++)
        wb[p] = *(const float4*)(W1 + (size_t)(br + p * 16) * H_ + n0 + bc4);

    for (int k0 = 0; k0 < D_; k0 += BK) {
        // store current tile to smem
        #pragma unroll
        for (int p = 0; p < 4; p++) {
            int m = lr + p * 32;
            As[lc + 0][m] = xa[p].x;
            As[lc + 1][m] = xa[p].y;
            As[lc + 2][m] = xa[p].z;
            As[lc + 3][m] = xa[p].w;
        }
        #pragma unroll
        for (int p = 0; p < 2; p++)
            *(float4*)&Bs[br + p * 16][bc4] = wb[p];
        __syncthreads();

        // prefetch next tile into regs
        if (k0 + BK < D_) {
            #pragma unroll
            for (int p = 0; p < 4; p++)
                xa[p] = *(const float4*)(xblk + (size_t)(lr + p * 32) * D_ + (k0 + BK) + lc);
            #pragma unroll
            for (int p = 0; p < 2; p++)
                wb[p] = *(const float4*)(W1 + (size_t)(k0 + BK + br + p * 16) * H_ + n0 + bc4);
        }

        // compute
        #pragma unroll
        for (int kk = 0; kk < BK; kk++) {
            ulonglong2 a01 = *(const ulonglong2*)&As[kk][ty * 8];
            ulonglong2 a23 = *(const ulonglong2*)&As[kk][ty * 8 + 4];
            float4 bv = *(const float4*)&Bs[kk][tx * 4];
            unsigned long long bd0, bd1, bd2, bd3;
            DUP2(bd0, __float_as_uint(bv.x));
            DUP2(bd1, __float_as_uint(bv.y));
            DUP2(bd2, __float_as_uint(bv.z));
            DUP2(bd3, __float_as_uint(bv.w));
            FMA2(acc[0][0], a01.x, bd0); FMA2(acc[0][1], a01.x, bd1);
            FMA2(acc[0][2], a01.x, bd2); FMA2(acc[0][3], a01.x, bd3);
            FMA2(acc[1][0], a01.y, bd0); FMA2(acc[1][1], a01.y, bd1);
            FMA2(acc[1][2], a01.y, bd2); FMA2(acc[1][3], a01.y, bd3);
            FMA2(acc[2][0], a23.x, bd0); FMA2(acc[2][1], a23.x, bd1);
            FMA2(acc[2][2], a23.x, bd2); FMA2(acc[2][3], a23.x, bd3);
            FMA2(acc[3][0], a23.y, bd0); FMA2(acc[3][1], a23.y, bd1);
            FMA2(acc[3][2], a23.y, bd2); FMA2(acc[3][3], a23.y, bd3);
        }
        __syncthreads();
    }

    // epilogue: bias + relu + per-thread partial chunk-sum over its 8 m-rows
    float b1v[4];
    #pragma unroll
    for (int j = 0; j < 4; j++) b1v[j] = b1[n0 + tx * 4 + j];

    float psum[4] = {0.f, 0.f, 0.f, 0.f};
    #pragma unroll
    for (int mp = 0; mp < 4; mp++) {
        #pragma unroll
        for (int j = 0; j < 4; j++) {
            unsigned long long v = acc[mp][j];
            float lo = __uint_as_float((unsigned)(v & 0xffffffffULL));
            float hi = __uint_as_float((unsigned)(v >> 32));
            psum[j] += fmaxf(lo + b1v[j], 0.f) + fmaxf(hi + b1v[j], 0.f);
        }
    }

    #pragma unroll
    for (int j = 0; j < 4; j++) Red[ty][tx * 4 + j] = psum[j];
    __syncthreads();

    if (tid < BN) {
        float s = 0.f;
        #pragma unroll
        for (int t = 0; t < 16; t++) s += Red[t][tid];
        g_hsum[(size_t)chunk * H_ + n0 + tid] = s;
    }
}

__global__ void gemm2_logits(const float* __restrict__ W2,
                             const float* __restrict__ b2) {
    const int bc = blockIdx.x;     // 0..255
    const int tid = threadIdx.x;   // 128 threads
    const float* hs = g_hsum + (size_t)bc * H_;

    float acc[E_];
    #pragma unroll
    for (int e = 0; e < E_; e++) acc[e] = 0.f;

    for (int j = tid; j < H_; j += 128) {
        float h = hs[j];
        float4 w0 = *(const float4*)(W2 + (size_t)j * E_);
        float4 w1 = *(const float4*)(W2 + (size_t)j * E_ + 4);
        acc[0] += h * w0.x; acc[1] += h * w0.y; acc[2] += h * w0.z; acc[3] += h * w0.w;
        acc[4] += h * w1.x; acc[5] += h * w1.y; acc[6] += h * w1.z; acc[7] += h * w1.w;
    }

    #pragma unroll
    for (int off = 16; off; off >>= 1)
        #pragma unroll
        for (int e = 0; e < E_; e++)
            acc[e] += __shfl_down_sync(0xffffffffu, acc[e], off);

    __shared__ float sred[4][E_];
    if ((tid & 31) == 0) {
        #pragma unroll
        for (int e = 0; e < E_; e++) sred[tid >> 5][e] = acc[e];
    }
    __syncthreads();
    if (tid < E_) {
        float s = sred[0][tid] + sred[1][tid] + sred[2][tid] + sred[3][tid];
        g_clogits[bc * E_ + tid] = s * (1.0f / (float)CHUNK_) + b2[tid];
    }
}

__global__ void hysteresis_scan(float* __restrict__ out, int out_size) {
    int b = threadIdx.x;
    if (b >= B_) return;
    const float* cl = g_clogits + b * 32 * E_;

    // chunk 0: plain argmax (first-max tie-break, ascending strict >)
    int prev = 0;
    {
        float best = cl[0];
        #pragma unroll
        for (int e = 1; e < E_; e++)
            if (cl[e] > best) { best = cl[e]; prev = e; }
    }
    g_eidx[b * 32] = prev;

    for (int c = 1; c < 32; c++) {
        const float* l = cl + c * E_;
        int ce = 0; float best = l[0];
        #pragma unroll
        for (int e = 1; e < E_; e++)
            if (l[e] > best) { best = l[e]; ce = e; }
        if (l[ce] - l[prev] > TAU_) prev = ce;
        g_eidx[b * 32 + c] = prev;
    }

    // expert_indices tail (as float), if the output buffer has room for it
    if (out_size >= B_ * S_ * E_ + NCHUNK_) {
        for (int c = 0; c < 32; c++)
            out[B_ * S_ * E_ + b * 32 + c] = (float)g_eidx[b * 32 + c];
    }
}

__global__ void fill_routing(float* __restrict__ out) {
    // one float4 per thread; 2 float4 per token; 65536 float4 total
    int q = blockIdx.x * blockDim.x + threadIdx.x;
    int token = q >> 1;
    int e0 = (q & 1) * 4;
    int idx = g_eidx[token >> 7];   // token/CHUNK
    float4 v;
    v.x = (e0 + 0 == idx) ? 1.0f : 0.0f;
    v.y = (e0 + 1 == idx) ? 1.0f : 0.0f;
    v.z = (e0 + 2 == idx) ? 1.0f : 0.0f;
    v.w = (e0 + 3 == idx) ? 1.0f : 0.0f;
    ((float4*)out)[q] = v;
}

extern "C" void kernel_launch(void* const* d_in, const int* in_sizes, int n_in,
                              void* d_out, int out_size) {
    const float* x  = (const float*)d_in[0];   // [8,4096,2048]
    const float* W1 = (const float*)d_in[1];   // [2048,1024]
    const float* b1 = (const float*)d_in[2];   // [1024]
    const float* W2 = (const float*)d_in[3];   // [1024,8]
    const float* b2 = (const float*)d_in[4];   // [8]
    float* out = (float*)d_out;

    dim3 g1(H_ / BN, NCHUNK_);  // (16, 256)
    gemm1_relu_chunksum<<<g1, 256>>>(x, W1, b1);
    gemm2_logits<<<NCHUNK_, 128>>>(W2, b2);
    hysteresis_scan<<<1, 32>>>(out, out_size);
    fill_routing<<<(B_ * S_ * E_ / 4) / 256, 256>>>(out);
}

// round 4
// speedup vs baseline: 2.0278x; 2.0278x over previous
#include <cuda_runtime.h>
#include <cuda_fp16.h>
#include <cstdint>

// ChunkStickyRouter on GB300 (sm_103a) — legacy mma.sync fp16 3-product split
// B=8, S=4096, D=2048, H=1024, E=8, CHUNK=128, TAU=0.7

#define B_  8
#define S_  4096
#define D_  2048
#define H_  1024
#define E_  8
#define CHUNK_ 128
#define NCHUNK_ 256
#define TAU_ 0.7f

// GEMM1 tiling
#define BM_ 128
#define BN_ 128
#define BK_ 32
#define NKC_ (D_ / BK_)        // 64
#define STAGES_ 3
#define ROWB_ 80               // smem row stride (bytes): 5*16 -> conflict-free LDSM
#define SPLIT_SZ_ (128 * ROWB_)        // 10240 B  (one 128-row fp16 tile)
#define STAGE_SZ_ (4 * SPLIT_SZ_)      // A_hi, A_lo, B_hi, B_lo = 40960 B
#define SM_B1_   (STAGES_ * STAGE_SZ_) // 122880
#define SM_PART_ (SM_B1_ + 512)
#define SMEM_TOTAL_ (SM_PART_ + 1024)  // 124416

// device scratch (pre-split fp16 operands)
__device__ __half g_x_hi[(size_t)B_ * S_ * D_];   // 128 MB
__device__ __half g_x_lo[(size_t)B_ * S_ * D_];   // 128 MB
__device__ __half g_w1t_hi[(size_t)H_ * D_];      // 4 MB, [n][k]
__device__ __half g_w1t_lo[(size_t)H_ * D_];
__device__ float  g_hsum[NCHUNK_ * H_];
__device__ float  g_clogits[NCHUNK_ * E_];
__device__ int    g_eidx[NCHUNK_];

// ---------------- PTX helpers ----------------
__device__ __forceinline__ uint32_t smem_to_u32(const void* p) {
    uint32_t a;
    asm("{ .reg .u64 t; cvta.to.shared.u64 t, %1; cvt.u32.u64 %0, t; }" : "=r"(a) : "l"(p));
    return a;
}
#define CP_ASYNC16(dst, src) \
    asm volatile("cp.async.cg.shared.global [%0], [%1], 16;" :: "r"(dst), "l"(src))
#define CP_COMMIT() asm volatile("cp.async.commit_group;" ::: "memory")
#define CP_WAIT1()  asm volatile("cp.async.wait_group 1;" ::: "memory")

#define LDSM4(r, a) \
    asm volatile("ldmatrix.sync.aligned.m8n8.x4.shared.b16 {%0,%1,%2,%3}, [%4];" \
        : "=r"((r)[0]), "=r"((r)[1]), "=r"((r)[2]), "=r"((r)[3]) : "r"(a))
#define LDSM2(r, a) \
    asm volatile("ldmatrix.sync.aligned.m8n8.x2.shared.b16 {%0,%1}, [%2];" \
        : "=r"((r)[0]), "=r"((r)[1]) : "r"(a))

#define MMA16816(d, a, b) \
    asm volatile("mma.sync.aligned.m16n8k16.row.col.f32.f16.f16.f32 " \
        "{%0,%1,%2,%3}, {%4,%5,%6,%7}, {%8,%9}, {%0,%1,%2,%3};" \
        : "+f"((d)[0]), "+f"((d)[1]), "+f"((d)[2]), "+f"((d)[3]) \
        : "r"((a)[0]), "r"((a)[1]), "r"((a)[2]), "r"((a)[3]), "r"((b)[0]), "r"((b)[1]))

// ---------------- prepass: split fp32 -> fp16 hi/lo ----------------
__global__ void split_x(const float4* __restrict__ x4) {
    size_t i = (size_t)blockIdx.x * blockDim.x + threadIdx.x;  // 16M float4
    float4 v = x4[i];
    __half hx = __float2half_rn(v.x), hy = __float2half_rn(v.y);
    __half hz = __float2half_rn(v.z), hw = __float2half_rn(v.w);
    __half lx = __float2half_rn(v.x - __half2float(hx));
    __half ly = __float2half_rn(v.y - __half2float(hy));
    __half lz = __float2half_rn(v.z - __half2float(hz));
    __half lw = __float2half_rn(v.w - __half2float(hw));
    ((__half2*)g_x_hi)[i * 2 + 0] = __halves2half2(hx, hy);
    ((__half2*)g_x_hi)[i * 2 + 1] = __halves2half2(hz, hw);
    ((__half2*)g_x_lo)[i * 2 + 0] = __halves2half2(lx, ly);
    ((__half2*)g_x_lo)[i * 2 + 1] = __halves2half2(lz, lw);
}

// W1 [k=2048][n=1024] fp32 -> W1^T [n][k] fp16 hi/lo
__global__ void split_w1(const float* __restrict__ W1) {
    __shared__ float t[32][33];
    int n0 = blockIdx.x * 32, k0 = blockIdx.y * 32;
    int tx = threadIdx.x, ty = threadIdx.y;
    #pragma unroll
    for (int i = 0; i < 4; i++)
        t[ty + i * 8][tx] = W1[(size_t)(k0 + ty + i * 8) * H_ + n0 + tx];
    __syncthreads();
    #pragma unroll
    for (int i = 0; i < 4; i++) {
        int n = ty + i * 8, k = tx;
        float v = t[k][n];
        __half hi = __float2half_rn(v);
        __half lo = __float2half_rn(v - __half2float(hi));
        g_w1t_hi[(size_t)(n0 + n) * D_ + k0 + k] = hi;
        g_w1t_lo[(size_t)(n0 + n) * D_ + k0 + k] = lo;
    }
}

// ---------------- GEMM1: relu(x@W1+b1) with fused chunk column-sum ----------------
__global__ __launch_bounds__(256, 1)
void gemm1_mma(const float* __restrict__ b1) {
    extern __shared__ __align__(1024) char smem[];
    const uint32_t sb = smem_to_u32(smem);
    const int tid = threadIdx.x;
    const int lane = tid & 31, wid = tid >> 5;
    const int wm = wid & 1, wn = wid >> 1;       // warp grid 2(m) x 4(n)
    const int n0 = blockIdx.x * BN_;
    const int chunk = blockIdx.y;
    const int m0 = chunk * BM_;

    if (tid < 128) ((float*)(smem + SM_B1_))[tid] = b1[n0 + tid];

    // ---- per-thread cp.async indices (4 A-chunks + 4 B-chunks of 16B) ----
    const char* srcA[4]; uint32_t dstA[4];
    const char* srcB[4]; uint32_t dstB[4];
    #pragma unroll
    for (int j = 0; j < 4; j++) {
        int q = tid + j * 256;                 // 0..1023
        int split = q >> 9, row = (q >> 2) & 127, k16 = q & 3;
        const __half* base = split ? g_x_lo : g_x_hi;
        srcA[j] = (const char*)(base + (size_t)(m0 + row) * D_ + k16 * 8);
        dstA[j] = sb + split * SPLIT_SZ_ + row * ROWB_ + k16 * 16;
        const __half* wb = split ? g_w1t_lo : g_w1t_hi;
        srcB[j] = (const char*)(wb + (size_t)(n0 + row) * D_ + k16 * 8);
        dstB[j] = sb + 2 * SPLIT_SZ_ + split * SPLIT_SZ_ + row * ROWB_ + k16 * 16;
    }

    // ---- per-thread ldmatrix offsets ----
    const uint32_t a_off = (uint32_t)((wm * 64 + (lane & 15)) * ROWB_ + (lane >> 4) * 16);
    const uint32_t b_off = (uint32_t)(2 * SPLIT_SZ_ + (wn * 32 + (lane & 7)) * ROWB_ + ((lane >> 3) & 1) * 16);

    float acc[4][4][4];
    #pragma unroll
    for (int a = 0; a < 4; a++)
        #pragma unroll
        for (int b = 0; b < 4; b++)
            #pragma unroll
            for (int c = 0; c < 4; c++) acc[a][b][c] = 0.f;

    // prologue: stages 0,1
    #pragma unroll
    for (int s = 0; s < 2; s++) {
        uint32_t sbase = s * STAGE_SZ_;
        #pragma unroll
        for (int j = 0; j < 4; j++) {
            CP_ASYNC16(dstA[j] + sbase, srcA[j] + s * 64);
            CP_ASYNC16(dstB[j] + sbase, srcB[j] + s * 64);
        }
        CP_COMMIT();
    }

    int buf = 0;
    for (int ck = 0; ck < NKC_; ck++) {
        CP_WAIT1();
        __syncthreads();

        // issue stage ck+2 into buffer (ck+2)%3
        if (ck + 2 < NKC_) {
            int nb = buf + 2; if (nb >= 3) nb -= 3;
            uint32_t sbase = nb * STAGE_SZ_;
            #pragma unroll
            for (int j = 0; j < 4; j++) {
                CP_ASYNC16(dstA[j] + sbase, srcA[j] + (size_t)(ck + 2) * 64);
                CP_ASYNC16(dstB[j] + sbase, srcB[j] + (size_t)(ck + 2) * 64);
            }
        }
        CP_COMMIT();

        // compute on buffer buf
        const uint32_t bufbase = sb + buf * STAGE_SZ_;
        #pragma unroll
        for (int kk = 0; kk < 2; kk++) {
            uint32_t ah[4][4], al[4][4], bh[4][2], bl[4][2];
            uint32_t ab = bufbase + a_off + kk * 32;
            uint32_t bb = bufbase + b_off + kk * 32;
            #pragma unroll
            for (int mt = 0; mt < 4; mt++) LDSM4(ah[mt], ab + mt * (16 * ROWB_));
            #pragma unroll
            for (int mt = 0; mt < 4; mt++) LDSM4(al[mt], ab + SPLIT_SZ_ + mt * (16 * ROWB_));
            #pragma unroll
            for (int nt = 0; nt < 4; nt++) LDSM2(bh[nt], bb + nt * (8 * ROWB_));
            #pragma unroll
            for (int nt = 0; nt < 4; nt++) LDSM2(bl[nt], bb + SPLIT_SZ_ + nt * (8 * ROWB_));
            #pragma unroll
            for (int mt = 0; mt < 4; mt++)
                #pragma unroll
                for (int nt = 0; nt < 4; nt++) {
                    MMA16816(acc[mt][nt], ah[mt], bh[nt]);
                    MMA16816(acc[mt][nt], ah[mt], bl[nt]);
                    MMA16816(acc[mt][nt], al[mt], bh[nt]);
                }
        }
        buf++; if (buf >= 3) buf = 0;
    }

    // ---- epilogue: relu(acc + b1), column sums over the 128-row chunk ----
    const float* sb1f = (const float*)(smem + SM_B1_);
    float csum[4][2];
    #pragma unroll
    for (int nt = 0; nt < 4; nt++) { csum[nt][0] = 0.f; csum[nt][1] = 0.f; }
    #pragma unroll
    for (int nt = 0; nt < 4; nt++) {
        int col = wn * 32 + nt * 8 + (lane & 3) * 2;
        float bv0 = sb1f[col], bv1 = sb1f[col + 1];
        #pragma unroll
        for (int mt = 0; mt < 4; mt++) {
            csum[nt][0] += fmaxf(acc[mt][nt][0] + bv0, 0.f) + fmaxf(acc[mt][nt][2] + bv0, 0.f);
            csum[nt][1] += fmaxf(acc[mt][nt][1] + bv1, 0.f) + fmaxf(acc[mt][nt][3] + bv1, 0.f);
        }
    }
    #pragma unroll
    for (int nt = 0; nt < 4; nt++)
        #pragma unroll
        for (int r = 0; r < 2; r++) {
            csum[nt][r] += __shfl_xor_sync(0xffffffffu, csum[nt][r], 4);
            csum[nt][r] += __shfl_xor_sync(0xffffffffu, csum[nt][r], 8);
            csum[nt][r] += __shfl_xor_sync(0xffffffffu, csum[nt][r], 16);
        }
    float* part = (float*)(smem + SM_PART_);
    __syncthreads();   // everyone past the main loop before reusing part region
    if (lane < 4) {
        #pragma unroll
        for (int nt = 0; nt < 4; nt++) {
            int col = wn * 32 + nt * 8 + lane * 2;
            part[wm * 128 + col] = csum[nt][0];
            part[wm * 128 + col + 1] = csum[nt][1];
        }
    }
    __syncthreads();
    if (tid < 128)
        g_hsum[(size_t)chunk * H_ + n0 + tid] = part[tid] + part[128 + tid];
}

// ---------------- GEMM2: chunk_logits = g_hsum @ W2 / 128 + b2 ----------------
__global__ void gemm2_logits(const float* __restrict__ W2,
                             const float* __restrict__ b2) {
    const int bc = blockIdx.x;
    const int tid = threadIdx.x;
    const float* hs = g_hsum + (size_t)bc * H_;

    float acc[E_];
    #pragma unroll
    for (int e = 0; e < E_; e++) acc[e] = 0.f;

    for (int j = tid; j < H_; j += 128) {
        float h = hs[j];
        float4 w0 = *(const float4*)(W2 + (size_t)j * E_);
        float4 w1 = *(const float4*)(W2 + (size_t)j * E_ + 4);
        acc[0] += h * w0.x; acc[1] += h * w0.y; acc[2] += h * w0.z; acc[3] += h * w0.w;
        acc[4] += h * w1.x; acc[5] += h * w1.y; acc[6] += h * w1.z; acc[7] += h * w1.w;
    }
    #pragma unroll
    for (int off = 16; off; off >>= 1)
        #pragma unroll
        for (int e = 0; e < E_; e++)
            acc[e] += __shfl_down_sync(0xffffffffu, acc[e], off);

    __shared__ float sred[4][E_];
    if ((tid & 31) == 0) {
        #pragma unroll
        for (int e = 0; e < E_; e++) sred[tid >> 5][e] = acc[e];
    }
    __syncthreads();
    if (tid < E_) {
        float s = sred[0][tid] + sred[1][tid] + sred[2][tid] + sred[3][tid];
        g_clogits[bc * E_ + tid] = s * (1.0f / (float)CHUNK_) + b2[tid];
    }
}

__global__ void hysteresis_scan(float* __restrict__ out, int out_size) {
    int b = threadIdx.x;
    if (b >= B_) return;
    const float* cl = g_clogits + b * 32 * E_;

    int prev = 0;
    {
        float best = cl[0];
        #pragma unroll
        for (int e = 1; e < E_; e++)
            if (cl[e] > best) { best = cl[e]; prev = e; }
    }
    g_eidx[b * 32] = prev;

    for (int c = 1; c < 32; c++) {
        const float* l = cl + c * E_;
        int ce = 0; float best = l[0];
        #pragma unroll
        for (int e = 1; e < E_; e++)
            if (l[e] > best) { best = l[e]; ce = e; }
        if (l[ce] - l[prev] > TAU_) prev = ce;
        g_eidx[b * 32 + c] = prev;
    }
    if (out_size >= B_ * S_ * E_ + NCHUNK_) {
        for (int c = 0; c < 32; c++)
            out[B_ * S_ * E_ + b * 32 + c] = (float)g_eidx[b * 32 + c];
    }
}

__global__ void fill_routing(float* __restrict__ out) {
    int q = blockIdx.x * blockDim.x + threadIdx.x;
    int token = q >> 1;
    int e0 = (q & 1) * 4;
    int idx = g_eidx[token >> 7];
    float4 v;
    v.x = (e0 + 0 == idx) ? 1.0f : 0.0f;
    v.y = (e0 + 1 == idx) ? 1.0f : 0.0f;
    v.z = (e0 + 2 == idx) ? 1.0f : 0.0f;
    v.w = (e0 + 3 == idx) ? 1.0f : 0.0f;
    ((float4*)out)[q] = v;
}

extern "C" void kernel_launch(void* const* d_in, const int* in_sizes, int n_in,
                              void* d_out, int out_size) {
    const float* x  = (const float*)d_in[0];
    const float* W1 = (const float*)d_in[1];
    const float* b1 = (const float*)d_in[2];
    const float* W2 = (const float*)d_in[3];
    const float* b2 = (const float*)d_in[4];
    float* out = (float*)d_out;

    cudaFuncSetAttribute(gemm1_mma, cudaFuncAttributeMaxDynamicSharedMemorySize, SMEM_TOTAL_);

    split_x<<<(B_ * S_ * D_ / 4) / 256, 256>>>((const float4*)x);
    split_w1<<<dim3(H_ / 32, D_ / 32), dim3(32, 8)>>>(W1);
    gemm1_mma<<<dim3(H_ / BN_, NCHUNK_), 256, SMEM_TOTAL_>>>(b1);
    gemm2_logits<<<NCHUNK_, 128>>>(W2, b2);
    hysteresis_scan<<<1, 32>>>(out, out_size);
    fill_routing<<<(B_ * S_ * E_ / 4) / 256, 256>>>(out);
}

// round 5
// speedup vs baseline: 2.2037x; 1.0867x over previous
#include <cuda_runtime.h>
#include <cuda_fp16.h>
#include <cstdint>

// ChunkStickyRouter on GB300 (sm_103a) — mma.sync fp16 3-product split, 512-thr CTA
// B=8, S=4096, D=2048, H=1024, E=8, CHUNK=128, TAU=0.7

#define B_  8
#define S_  4096
#define D_  2048
#define H_  1024
#define E_  8
#define CHUNK_ 128
#define NCHUNK_ 256
#define TAU_ 0.7f

// GEMM1 tiling
#define BM_ 128
#define BN_ 256
#define BK_ 32
#define NKC_ (D_ / BK_)        // 64
#define NTHR_ 512
#define ROWB_ 80               // smem row stride (bytes): conflict-free LDSM
#define ASPLIT_ (128 * ROWB_)          // 10240 B per A split tile
#define BSPLIT_ (256 * ROWB_)          // 20480 B per B split tile
#define AREG_   (2 * ASPLIT_)          // 20480
#define STAGE_SZ_ (AREG_ + 2 * BSPLIT_) // 61440
#define SM_B1_   (3 * STAGE_SZ_)        // 184320
#define SM_PART_ (SM_B1_ + 1024)
#define SMEM_TOTAL_ (SM_PART_ + 2048)   // 187392

// device scratch (pre-split fp16 operands)
__device__ __half g_x_hi[(size_t)B_ * S_ * D_];
__device__ __half g_x_lo[(size_t)B_ * S_ * D_];
__device__ __half g_w1t_hi[(size_t)H_ * D_];      // [n][k]
__device__ __half g_w1t_lo[(size_t)H_ * D_];
__device__ float  g_hsum[NCHUNK_ * H_];
__device__ float  g_clogits[NCHUNK_ * E_];
__device__ int    g_eidx[NCHUNK_];

// ---------------- PTX helpers ----------------
__device__ __forceinline__ uint32_t smem_to_u32(const void* p) {
    uint32_t a;
    asm("{ .reg .u64 t; cvta.to.shared.u64 t, %1; cvt.u32.u64 %0, t; }" : "=r"(a) : "l"(p));
    return a;
}
#define CP_ASYNC16(dst, src) \
    asm volatile("cp.async.cg.shared.global [%0], [%1], 16;" :: "r"(dst), "l"(src))
#define CP_COMMIT() asm volatile("cp.async.commit_group;" ::: "memory")
#define CP_WAIT1()  asm volatile("cp.async.wait_group 1;" ::: "memory")

#define LDSM4(r, a) \
    asm volatile("ldmatrix.sync.aligned.m8n8.x4.shared.b16 {%0,%1,%2,%3}, [%4];" \
        : "=r"((r)[0]), "=r"((r)[1]), "=r"((r)[2]), "=r"((r)[3]) : "r"(a))
#define LDSM2(r, a) \
    asm volatile("ldmatrix.sync.aligned.m8n8.x2.shared.b16 {%0,%1}, [%2];" \
        : "=r"((r)[0]), "=r"((r)[1]) : "r"(a))

#define MMA16816(d, a, b) \
    asm volatile("mma.sync.aligned.m16n8k16.row.col.f32.f16.f16.f32 " \
        "{%0,%1,%2,%3}, {%4,%5,%6,%7}, {%8,%9}, {%0,%1,%2,%3};" \
        : "+f"((d)[0]), "+f"((d)[1]), "+f"((d)[2]), "+f"((d)[3]) \
        : "r"((a)[0]), "r"((a)[1]), "r"((a)[2]), "r"((a)[3]), "r"((b)[0]), "r"((b)[1]))

// ---------------- prepass: split fp32 -> fp16 hi/lo ----------------
__global__ void split_x(const float4* __restrict__ x4) {
    size_t i = (size_t)blockIdx.x * blockDim.x + threadIdx.x;
    float4 v = x4[i];
    __half hx = __float2half_rn(v.x), hy = __float2half_rn(v.y);
    __half hz = __float2half_rn(v.z), hw = __float2half_rn(v.w);
    __half lx = __float2half_rn(v.x - __half2float(hx));
    __half ly = __float2half_rn(v.y - __half2float(hy));
    __half lz = __float2half_rn(v.z - __half2float(hz));
    __half lw = __float2half_rn(v.w - __half2float(hw));
    ((__half2*)g_x_hi)[i * 2 + 0] = __halves2half2(hx, hy);
    ((__half2*)g_x_hi)[i * 2 + 1] = __halves2half2(hz, hw);
    ((__half2*)g_x_lo)[i * 2 + 0] = __halves2half2(lx, ly);
    ((__half2*)g_x_lo)[i * 2 + 1] = __halves2half2(lz, lw);
}

__global__ void split_w1(const float* __restrict__ W1) {
    __shared__ float t[32][33];
    int n0 = blockIdx.x * 32, k0 = blockIdx.y * 32;
    int tx = threadIdx.x, ty = threadIdx.y;
    #pragma unroll
    for (int i = 0; i < 4; i++)
        t[ty + i * 8][tx] = W1[(size_t)(k0 + ty + i * 8) * H_ + n0 + tx];
    __syncthreads();
    #pragma unroll
    for (int i = 0; i < 4; i++) {
        int n = ty + i * 8, k = tx;
        float v = t[k][n];
        __half hi = __float2half_rn(v);
        __half lo = __float2half_rn(v - __half2float(hi));
        g_w1t_hi[(size_t)(n0 + n) * D_ + k0 + k] = hi;
        g_w1t_lo[(size_t)(n0 + n) * D_ + k0 + k] = lo;
    }
}

// ---------------- GEMM1: relu(x@W1+b1) with fused chunk column-sum ----------------
__global__ __launch_bounds__(NTHR_, 1)
void gemm1_mma(const float* __restrict__ b1) {
    extern __shared__ __align__(1024) char smem[];
    const uint32_t sb = smem_to_u32(smem);
    const int tid = threadIdx.x;
    const int lane = tid & 31, wid = tid >> 5;      // 16 warps
    const int wm = wid & 1, wn = wid >> 1;          // 2(m) x 8(n)
    const int n0 = blockIdx.x * BN_;
    const int chunk = blockIdx.y;
    const int m0 = chunk * BM_;

    if (tid < BN_) ((float*)(smem + SM_B1_))[tid] = b1[n0 + tid];

    // ---- per-thread cp.async indices: 2 A-chunks + 4 B-chunks of 16B ----
    const char* srcA[2]; uint32_t dstA[2];
    const char* srcB[4]; uint32_t dstB[4];
    #pragma unroll
    for (int j = 0; j < 2; j++) {
        int q = tid + j * NTHR_;               // 0..1023
        int split = q >> 9, row = (q >> 2) & 127, k16 = q & 3;
        const __half* base = split ? g_x_lo : g_x_hi;
        srcA[j] = (const char*)(base + (size_t)(m0 + row) * D_ + k16 * 8);
        dstA[j] = sb + split * ASPLIT_ + row * ROWB_ + k16 * 16;
    }
    #pragma unroll
    for (int j = 0; j < 4; j++) {
        int q = tid + j * NTHR_;               // 0..2047
        int split = q >> 10, row = (q >> 2) & 255, k16 = q & 3;
        const __half* wb = split ? g_w1t_lo : g_w1t_hi;
        srcB[j] = (const char*)(wb + (size_t)(n0 + row) * D_ + k16 * 8);
        dstB[j] = sb + AREG_ + split * BSPLIT_ + row * ROWB_ + k16 * 16;
    }

    // ---- per-thread ldmatrix offsets ----
    const uint32_t a_off = (uint32_t)((wm * 64 + (lane & 15)) * ROWB_ + (lane >> 4) * 16);
    const uint32_t b_off = (uint32_t)(AREG_ + (wn * 32 + (lane & 7)) * ROWB_ + ((lane >> 3) & 1) * 16);

    float acc[4][4][4];
    #pragma unroll
    for (int a = 0; a < 4; a++)
        #pragma unroll
        for (int b = 0; b < 4; b++)
            #pragma unroll
            for (int c = 0; c < 4; c++) acc[a][b][c] = 0.f;

    // prologue: stages 0,1
    #pragma unroll
    for (int s = 0; s < 2; s++) {
        uint32_t sbase = s * STAGE_SZ_;
        #pragma unroll
        for (int j = 0; j < 2; j++) CP_ASYNC16(dstA[j] + sbase, srcA[j] + s * 64);
        #pragma unroll
        for (int j = 0; j < 4; j++) CP_ASYNC16(dstB[j] + sbase, srcB[j] + s * 64);
        CP_COMMIT();
    }

    int buf = 0;
    for (int ck = 0; ck < NKC_; ck++) {
        CP_WAIT1();
        __syncthreads();

        if (ck + 2 < NKC_) {
            int nb = buf + 2; if (nb >= 3) nb -= 3;
            uint32_t sbase = nb * STAGE_SZ_;
            #pragma unroll
            for (int j = 0; j < 2; j++) CP_ASYNC16(dstA[j] + sbase, srcA[j] + (size_t)(ck + 2) * 64);
            #pragma unroll
            for (int j = 0; j < 4; j++) CP_ASYNC16(dstB[j] + sbase, srcB[j] + (size_t)(ck + 2) * 64);
        }
        CP_COMMIT();

        const uint32_t bufbase = sb + buf * STAGE_SZ_;
        #pragma unroll
        for (int kk = 0; kk < 2; kk++) {
            uint32_t ah[4][4], al[4][4];
            uint32_t ab = bufbase + a_off + kk * 32;
            uint32_t bb = bufbase + b_off + kk * 32;
            #pragma unroll
            for (int mt = 0; mt < 4; mt++) LDSM4(ah[mt], ab + mt * (16 * ROWB_));
            #pragma unroll
            for (int mt = 0; mt < 4; mt++) LDSM4(al[mt], ab + ASPLIT_ + mt * (16 * ROWB_));
            #pragma unroll
            for (int nt = 0; nt < 4; nt++) {
                uint32_t bh[2], bl[2];
                LDSM2(bh, bb + nt * (8 * ROWB_));
                LDSM2(bl, bb + BSPLIT_ + nt * (8 * ROWB_));
                #pragma unroll
                for (int mt = 0; mt < 4; mt++) {
                    MMA16816(acc[mt][nt], ah[mt], bh);
                    MMA16816(acc[mt][nt], ah[mt], bl);
                    MMA16816(acc[mt][nt], al[mt], bh);
                }
            }
        }
        buf++; if (buf >= 3) buf = 0;
    }

    // ---- epilogue: relu(acc + b1), column sums over the 128-row chunk ----
    const float* sb1f = (const float*)(smem + SM_B1_);
    float csum[4][2];
    #pragma unroll
    for (int nt = 0; nt < 4; nt++) { csum[nt][0] = 0.f; csum[nt][1] = 0.f; }
    #pragma unroll
    for (int nt = 0; nt < 4; nt++) {
        int col = wn * 32 + nt * 8 + (lane & 3) * 2;
        float bv0 = sb1f[col], bv1 = sb1f[col + 1];
        #pragma unroll
        for (int mt = 0; mt < 4; mt++) {
            csum[nt][0] += fmaxf(acc[mt][nt][0] + bv0, 0.f) + fmaxf(acc[mt][nt][2] + bv0, 0.f);
            csum[nt][1] += fmaxf(acc[mt][nt][1] + bv1, 0.f) + fmaxf(acc[mt][nt][3] + bv1, 0.f);
        }
    }
    #pragma unroll
    for (int nt = 0; nt < 4; nt++)
        #pragma unroll
        for (int r = 0; r < 2; r++) {
            csum[nt][r] += __shfl_xor_sync(0xffffffffu, csum[nt][r], 4);
            csum[nt][r] += __shfl_xor_sync(0xffffffffu, csum[nt][r], 8);
            csum[nt][r] += __shfl_xor_sync(0xffffffffu, csum[nt][r], 16);
        }
    float* part = (float*)(smem + SM_PART_);    // [2][256]
    __syncthreads();
    if (lane < 4) {
        #pragma unroll
        for (int nt = 0; nt < 4; nt++) {
            int col = wn * 32 + nt * 8 + lane * 2;
            part[wm * BN_ + col] = csum[nt][0];
            part[wm * BN_ + col + 1] = csum[nt][1];
        }
    }
    __syncthreads();
    if (tid < BN_)
        g_hsum[(size_t)chunk * H_ + n0 + tid] = part[tid] + part[BN_ + tid];
}

// ---------------- GEMM2: chunk_logits = g_hsum @ W2 / 128 + b2 ----------------
__global__ void gemm2_logits(const float* __restrict__ W2,
                             const float* __restrict__ b2) {
    const int bc = blockIdx.x;
    const int tid = threadIdx.x;
    const float* hs = g_hsum + (size_t)bc * H_;

    float acc[E_];
    #pragma unroll
    for (int e = 0; e < E_; e++) acc[e] = 0.f;

    for (int j = tid; j < H_; j += 128) {
        float h = hs[j];
        float4 w0 = *(const float4*)(W2 + (size_t)j * E_);
        float4 w1 = *(const float4*)(W2 + (size_t)j * E_ + 4);
        acc[0] += h * w0.x; acc[1] += h * w0.y; acc[2] += h * w0.z; acc[3] += h * w0.w;
        acc[4] += h * w1.x; acc[5] += h * w1.y; acc[6] += h * w1.z; acc[7] += h * w1.w;
    }
    #pragma unroll
    for (int off = 16; off; off >>= 1)
        #pragma unroll
        for (int e = 0; e < E_; e++)
            acc[e] += __shfl_down_sync(0xffffffffu, acc[e], off);

    __shared__ float sred[4][E_];
    if ((tid & 31) == 0) {
        #pragma unroll
        for (int e = 0; e < E_; e++) sred[tid >> 5][e] = acc[e];
    }
    __syncthreads();
    if (tid < E_) {
        float s = sred[0][tid] + sred[1][tid] + sred[2][tid] + sred[3][tid];
        g_clogits[bc * E_ + tid] = s * (1.0f / (float)CHUNK_) + b2[tid];
    }
}

__global__ void hysteresis_scan(float* __restrict__ out, int out_size) {
    int b = threadIdx.x;
    if (b >= B_) return;
    const float* cl = g_clogits + b * 32 * E_;

    int prev = 0;
    {
        float best = cl[0];
        #pragma unroll
        for (int e = 1; e < E_; e++)
            if (cl[e] > best) { best = cl[e]; prev = e; }
    }
    g_eidx[b * 32] = prev;

    for (int c = 1; c < 32; c++) {
        const float* l = cl + c * E_;
        int ce = 0; float best = l[0];
        #pragma unroll
        for (int e = 1; e < E_; e++)
            if (l[e] > best) { best = l[e]; ce = e; }
        if (l[ce] - l[prev] > TAU_) prev = ce;
        g_eidx[b * 32 + c] = prev;
    }
    if (out_size >= B_ * S_ * E_ + NCHUNK_) {
        for (int c = 0; c < 32; c++)
            out[B_ * S_ * E_ + b * 32 + c] = (float)g_eidx[b * 32 + c];
    }
}

__global__ void fill_routing(float* __restrict__ out) {
    int q = blockIdx.x * blockDim.x + threadIdx.x;
    int token = q >> 1;
    int e0 = (q & 1) * 4;
    int idx = g_eidx[token >> 7];
    float4 v;
    v.x = (e0 + 0 == idx) ? 1.0f : 0.0f;
    v.y = (e0 + 1 == idx) ? 1.0f : 0.0f;
    v.z = (e0 + 2 == idx) ? 1.0f : 0.0f;
    v.w = (e0 + 3 == idx) ? 1.0f : 0.0f;
    ((float4*)out)[q] = v;
}

extern "C" void kernel_launch(void* const* d_in, const int* in_sizes, int n_in,
                              void* d_out, int out_size) {
    const float* x  = (const float*)d_in[0];
    const float* W1 = (const float*)d_in[1];
    const float* b1 = (const float*)d_in[2];
    const float* W2 = (const float*)d_in[3];
    const float* b2 = (const float*)d_in[4];
    float* out = (float*)d_out;

    cudaFuncSetAttribute(gemm1_mma, cudaFuncAttributeMaxDynamicSharedMemorySize, SMEM_TOTAL_);

    split_x<<<(B_ * S_ * D_ / 4) / 256, 256>>>((const float4*)x);
    split_w1<<<dim3(H_ / 32, D_ / 32), dim3(32, 8)>>>(W1);
    gemm1_mma<<<dim3(H_ / BN_, NCHUNK_), NTHR_, SMEM_TOTAL_>>>(b1);
    gemm2_logits<<<NCHUNK_, 128>>>(W2, b2);
    hysteresis_scan<<<1, 32>>>(out, out_size);
    fill_routing<<<(B_ * S_ * E_ / 4) / 256, 256>>>(out);
}